// round 10
// baseline (speedup 1.0000x reference)
#include <cuda_runtime.h>
#include <cuda_fp16.h>
#include <cuda_bf16.h>
#include <cstdint>

// Problem constants
#define PB   128
#define PN   256
#define PD   1024
#define PH   16
#define PDK  64
#define PM   (PB*PN)   // 32768

// ---------------------------------------------------------------------------
// Global scratch
// ---------------------------------------------------------------------------
__device__ float g_Q[PM*PD];   // fp32 projections, row-major (b*N+n, e)
__device__ float g_K[PM*PD];
__device__ float g_V[PM*PD];

__device__ __half g_qh[PM*PD], g_ql[PM*PD];   // fp16 2-term splits of inputs
__device__ __half g_kh[PM*PD], g_kl[PM*PD];
__device__ __half g_vh[PM*PD], g_vl[PM*PD];
__device__ __half g_oh[PM*PD], g_ol[PM*PD];   // attention output split
__device__ __half g_w[4][PD*PD];              // weights: fp16 hi only

// ---------------------------------------------------------------------------
// helpers
// ---------------------------------------------------------------------------
__device__ __forceinline__ uint32_t smem_u32(const void* p) {
    uint32_t a;
    asm("{ .reg .u64 t; cvta.to.shared.u64 t, %1; cvt.u32.u64 %0, t; }"
        : "=r"(a) : "l"(p));
    return a;
}
// pack two floats -> f16x2 (low = x, high = y)
__device__ __forceinline__ uint32_t h2pk(float x, float y) {
    uint32_t r;
    asm("cvt.rn.f16x2.f32 %0, %2, %1;" : "=r"(r) : "f"(x), "f"(y));
    return r;
}
__device__ __forceinline__ float2 h2unpk(uint32_t v) {
    __half2 h;
    *reinterpret_cast<uint32_t*>(&h) = v;
    return __half22float2(h);
}
__device__ __forceinline__ void cpa16(uint32_t s, const void* g) {
    asm volatile("cp.async.cg.shared.global [%0], [%1], 16;"
                 :: "r"(s), "l"(g) : "memory");
}
__device__ __forceinline__ void ldsm4(uint32_t* r, uint32_t addr) {
    asm volatile("ldmatrix.sync.aligned.m8n8.x4.shared.b16 {%0,%1,%2,%3}, [%4];"
                 : "=r"(r[0]), "=r"(r[1]), "=r"(r[2]), "=r"(r[3]) : "r"(addr));
}
__device__ __forceinline__ void ldsm4t(uint32_t* r, uint32_t addr) {
    asm volatile("ldmatrix.sync.aligned.m8n8.x4.trans.shared.b16 {%0,%1,%2,%3}, [%4];"
                 : "=r"(r[0]), "=r"(r[1]), "=r"(r[2]), "=r"(r[3]) : "r"(addr));
}
__device__ __forceinline__ void mma_f16(float* c, const uint32_t* a,
                                        const uint32_t* b) {
    asm volatile("mma.sync.aligned.m16n8k16.row.col.f32.f16.f16.f32 "
                 "{%0,%1,%2,%3}, {%4,%5,%6,%7}, {%8,%9}, {%0,%1,%2,%3};"
                 : "+f"(c[0]), "+f"(c[1]), "+f"(c[2]), "+f"(c[3])
                 : "r"(a[0]), "r"(a[1]), "r"(a[2]), "r"(a[3]),
                   "r"(b[0]), "r"(b[1]));
}

// fast exp on FMA/ALU pipes
__device__ __forceinline__ float fexp(float x) {
    x = fmaxf(x, -80.0f);
    float y = x * 1.44269504089f;
    float t = y + 12582912.0f;
    int   n = __float_as_int(t) - 0x4B400000;
    float fn = t - 12582912.0f;
    float f = y - fn;
    float r = fmaf(f, 1.3333558e-3f, 9.6181291e-3f);
    r = fmaf(f, r, 5.5504108e-2f);
    r = fmaf(f, r, 2.4022650e-1f);
    r = fmaf(f, r, 6.9314718e-1f);
    r = fmaf(f, r, 1.0f);
    float s = __int_as_float((n + 127) << 23);
    return r * s;
}

// ---------------------------------------------------------------------------
// split2: fp32 -> fp16 hi + fp16 lo (residual)
// ---------------------------------------------------------------------------
__global__ __launch_bounds__(256)
void split2_f16(const float* __restrict__ src,
                __half* __restrict__ hi, __half* __restrict__ lo, int n4)
{
    int i = blockIdx.x * 256 + threadIdx.x;
    if (i >= n4) return;
    float4 v = ((const float4*)src)[i];
    uint32_t h01 = h2pk(v.x, v.y);
    uint32_t h23 = h2pk(v.z, v.w);
    float2 f01 = h2unpk(h01), f23 = h2unpk(h23);
    ((uint2*)hi)[i] = make_uint2(h01, h23);
    ((uint2*)lo)[i] = make_uint2(h2pk(v.x - f01.x, v.y - f01.y),
                                 h2pk(v.z - f23.x, v.w - f23.y));
}

// convert: fp32 -> fp16 (hi only, for weights)
__global__ __launch_bounds__(256)
void conv_f16(const float* __restrict__ src, __half* __restrict__ dst, int n4)
{
    int i = blockIdx.x * 256 + threadIdx.x;
    if (i >= n4) return;
    float4 v = ((const float4*)src)[i];
    ((uint2*)dst)[i] = make_uint2(h2pk(v.x, v.y), h2pk(v.z, v.w));
}

// ---------------------------------------------------------------------------
// GEMM: Y[m,e] = sum_d A[m,d]*B[e,d] + bias[e], fp16 2-term (A split, B hi).
// CTA tile 128x256, warp tile 64x64 (8 warps: 2m x 4n), KC=32,
// 4-stage cp.async pipeline, xor-swizzled 64B rows for ldmatrix.
// ---------------------------------------------------------------------------
#define GKC   32
#define GNK   (PD/GKC)          // 32 chunks
#define STGB  32768             // per-stage: Ah 8K | Al 8K | Bh 16K
#define NSTG  4
#define GEMM_SMEM (NSTG*STGB)   // 128 KB

__device__ __forceinline__ uint32_t sw_off(int r, int c16) {
    return (uint32_t)(r * 64 + ((c16 ^ ((r >> 1) & 3)) << 4));
}

__device__ __forceinline__ void gemm_load_stage(
    uint32_t sbase, int stage, int kk, int tid,
    const __half* Ah0, const __half* Al0, const __half* Bh0)
{
    const uint32_t sb = sbase + (uint32_t)stage * STGB;
    const int koff = kk * GKC;
#pragma unroll
    for (int it = 0; it < 2; ++it) {
        int ch = tid + 256 * it;
        int r = ch >> 2, c = ch & 3;
        const size_t g = (size_t)r * PD + koff + c * 8;
        uint32_t so = sw_off(r, c);
        cpa16(sb + so,        Ah0 + g);
        cpa16(sb + 8192 + so, Al0 + g);
    }
#pragma unroll
    for (int it = 0; it < 4; ++it) {
        int ch = tid + 256 * it;
        int r = ch >> 2, c = ch & 3;
        const size_t g = (size_t)r * PD + koff + c * 8;
        cpa16(sb + 16384 + sw_off(r, c), Bh0 + g);
    }
    asm volatile("cp.async.commit_group;" ::: "memory");
}

__global__ __launch_bounds__(256, 1)
void gemm_f16x2(const __half* __restrict__ Ah, const __half* __restrict__ Al,
                const __half* __restrict__ Bh,
                const float* __restrict__ bias, float* __restrict__ Y)
{
    extern __shared__ char smc[];
    const uint32_t sbase = smem_u32(smc);
    const int tid = threadIdx.x;
    const int wid = tid >> 5, lane = tid & 31;
    const int m0 = blockIdx.y * 128, n0 = blockIdx.x * 256;
    const int wm = wid & 1, wn = wid >> 1;   // 2m x 4n warps, each 64x64

    const __half* Ah0 = Ah + (size_t)m0 * PD;
    const __half* Al0 = Al + (size_t)m0 * PD;
    const __half* Bh0 = Bh + (size_t)n0 * PD;

    float acc[4][8][4];
#pragma unroll
    for (int mi = 0; mi < 4; ++mi)
#pragma unroll
        for (int ni = 0; ni < 8; ++ni)
#pragma unroll
            for (int q = 0; q < 4; ++q) acc[mi][ni][q] = 0.f;

    gemm_load_stage(sbase, 0, 0, tid, Ah0, Al0, Bh0);
    gemm_load_stage(sbase, 1, 1, tid, Ah0, Al0, Bh0);
    gemm_load_stage(sbase, 2, 2, tid, Ah0, Al0, Bh0);

    const int a_row  = wm * 64 + (lane & 15);
    const int a_c16h = lane >> 4;
    const int b_row  = wn * 64 + ((lane >> 4) << 3) + (lane & 7);
    const int b_c16h = (lane >> 3) & 1;

    for (int kk = 0; kk < GNK; ++kk) {
        if (kk < GNK - 2)       asm volatile("cp.async.wait_group 2;" ::: "memory");
        else if (kk == GNK - 2) asm volatile("cp.async.wait_group 1;" ::: "memory");
        else                    asm volatile("cp.async.wait_group 0;" ::: "memory");
        __syncthreads();

        if (kk + 3 < GNK)
            gemm_load_stage(sbase, (kk + 3) & 3, kk + 3, tid, Ah0, Al0, Bh0);

        const uint32_t sb = sbase + (uint32_t)(kk & 3) * STGB;
#pragma unroll
        for (int ks = 0; ks < 2; ++ks) {
            uint32_t ahi[4][4], alo[4][4];
            const int ac = ks * 2 + a_c16h;
#pragma unroll
            for (int mi = 0; mi < 4; ++mi) {
                uint32_t so = sw_off(a_row + mi * 16, ac);
                ldsm4(ahi[mi], sb + so);
                ldsm4(alo[mi], sb + 8192 + so);
            }
            const int bc = ks * 2 + b_c16h;
#pragma unroll
            for (int bi = 0; bi < 4; ++bi) {
                uint32_t bhi[4];
                ldsm4(bhi, sb + 16384 + sw_off(b_row + bi * 16, bc));
#pragma unroll
                for (int mi = 0; mi < 4; ++mi) {
#pragma unroll
                    for (int half = 0; half < 2; ++half) {
                        float* c4 = acc[mi][bi * 2 + half];
                        mma_f16(c4, ahi[mi], &bhi[half * 2]);
                        mma_f16(c4, alo[mi], &bhi[half * 2]);
                    }
                }
            }
        }
    }

    const int trow = lane >> 2;
    const int tcol = (lane & 3) * 2;
#pragma unroll
    for (int mi = 0; mi < 4; ++mi) {
        const int r0 = m0 + wm * 64 + mi * 16 + trow;
#pragma unroll
        for (int ni = 0; ni < 8; ++ni) {
            const int col = n0 + wn * 64 + ni * 8 + tcol;
            float bx = bias[col], by = bias[col + 1];
            float* c4 = acc[mi][ni];
            *(float2*)(Y + (size_t)r0 * PD + col) =
                make_float2(c4[0] + bx, c4[1] + by);
            *(float2*)(Y + (size_t)(r0 + 8) * PD + col) =
                make_float2(c4[2] + bx, c4[3] + by);
        }
    }
}

// ---------------------------------------------------------------------------
// Tensor-core attention: one CTA per (h,n), 256 threads (8 warps: 4m x 2n).
// Scores 128x128x64 (Q split fp16 x K hi), softmax (fexp),
// PV 128x64x128 (P split fp16 x V hi, ldmatrix.trans). fp16 hi/lo output.
// ---------------------------------------------------------------------------
#define AT_PITCH   144           // rows: 64 fp16 = 128B + 16 pad
#define AT_PPITCH  272           // P rows: 128 fp16 = 256B + 16 pad
#define AT_VH      0
#define AT_QH      18432
#define AT_QL      36864
#define AT_KH      55296         // end 73728
#define AT_PH      18432         // P overwrites Q/K region (V stays live)
#define AT_PL      53248         // end 88064
#define AT_RED     88064
#define AT_RED2    89088
#define AT_SMEM    90112

__global__ __launch_bounds__(256)
void attn_tc(const float* __restrict__ Q, const float* __restrict__ K,
             const float* __restrict__ V,
             __half* __restrict__ Oh, __half* __restrict__ Ol)
{
    extern __shared__ char sm[];
    const uint32_t sb = smem_u32(sm);
    const int tid = threadIdx.x;
    const int wid = tid >> 5, lane = tid & 31;
    const int wm = wid & 3, wn = wid >> 2;   // 4m x 2n
    const int hn = blockIdx.x;
    const int h  = hn >> 8;
    const int n  = hn & 255;
    const size_t rowoff = (size_t)n * PD + h * PDK;

    // ---- load fp32 Q/K/V tiles -> fp16 smem (Q split 2-term, K/V hi) ----
#pragma unroll
    for (int j = 0; j < 8; ++j) {
        int i = tid + 256 * j;
        int r = i >> 4, c4 = i & 15;
        size_t g = (size_t)r * (PD * PN) + rowoff + c4 * 4;
        uint32_t so = (uint32_t)(r * AT_PITCH + c4 * 8);
        {   // Q scaled by 1/8 (exact), split
            float4 v = *(const float4*)(Q + g);
            v.x *= 0.125f; v.y *= 0.125f; v.z *= 0.125f; v.w *= 0.125f;
            uint32_t h01 = h2pk(v.x, v.y), h23 = h2pk(v.z, v.w);
            float2 f01 = h2unpk(h01), f23 = h2unpk(h23);
            *(uint2*)(sm + AT_QH + so) = make_uint2(h01, h23);
            *(uint2*)(sm + AT_QL + so) =
                make_uint2(h2pk(v.x - f01.x, v.y - f01.y),
                           h2pk(v.z - f23.x, v.w - f23.y));
        }
        {   // K hi
            float4 v = *(const float4*)(K + g);
            *(uint2*)(sm + AT_KH + so) =
                make_uint2(h2pk(v.x, v.y), h2pk(v.z, v.w));
        }
        {   // V hi
            float4 v = *(const float4*)(V + g);
            *(uint2*)(sm + AT_VH + so) =
                make_uint2(h2pk(v.x, v.y), h2pk(v.z, v.w));
        }
    }
    __syncthreads();

    // ---- scores: S = Qs * K^T  (M=128, N=128, K=64) ----
    float sc[2][8][4];
#pragma unroll
    for (int mi = 0; mi < 2; ++mi)
#pragma unroll
        for (int ni = 0; ni < 8; ++ni)
#pragma unroll
            for (int q = 0; q < 4; ++q) sc[mi][ni][q] = 0.f;

    const int a_row = wm * 32 + (lane & 15);
    const int a_off = (lane >> 4) * 16;                          // bytes
    const int b_row = wn * 64 + ((lane >> 4) << 3) + (lane & 7);
    const int b_off = ((lane >> 3) & 1) * 16;                    // bytes

#pragma unroll
    for (int ks = 0; ks < 4; ++ks) {
        uint32_t ah[2][4], al[2][4];
#pragma unroll
        for (int mi = 0; mi < 2; ++mi) {
            uint32_t ad = sb + (uint32_t)((a_row + mi * 16) * AT_PITCH + ks * 32) + a_off;
            ldsm4(ah[mi], ad + AT_QH);
            ldsm4(al[mi], ad + AT_QL);
        }
#pragma unroll
        for (int bi = 0; bi < 4; ++bi) {
            uint32_t bh[4];
            ldsm4(bh, sb + (uint32_t)((b_row + bi * 16) * AT_PITCH + ks * 32) + b_off + AT_KH);
#pragma unroll
            for (int mi = 0; mi < 2; ++mi) {
#pragma unroll
                for (int half = 0; half < 2; ++half) {
                    float* c4 = sc[mi][bi * 2 + half];
                    mma_f16(c4, ah[mi], &bh[half * 2]);
                    mma_f16(c4, al[mi], &bh[half * 2]);
                }
            }
        }
    }

    // ---- softmax over rows (each thread: 16 cols x 4 rows) ----
    const int trow = lane >> 2;
    const int tcol = (lane & 3) * 2;
    float* red  = (float*)(sm + AT_RED);
    float* red2 = (float*)(sm + AT_RED2);

#pragma unroll
    for (int mi = 0; mi < 2; ++mi)
#pragma unroll
        for (int hr = 0; hr < 2; ++hr) {
            float m = -1e30f;
#pragma unroll
            for (int ni = 0; ni < 8; ++ni) {
                m = fmaxf(m, sc[mi][ni][hr * 2 + 0]);
                m = fmaxf(m, sc[mi][ni][hr * 2 + 1]);
            }
            m = fmaxf(m, __shfl_xor_sync(0xffffffffu, m, 1));
            m = fmaxf(m, __shfl_xor_sync(0xffffffffu, m, 2));
            int row = wm * 32 + mi * 16 + hr * 8 + trow;
            if ((lane & 3) == 0) red[row * 2 + wn] = m;
        }
    __syncthreads();

    float inv_[2][2];
#pragma unroll
    for (int mi = 0; mi < 2; ++mi)
#pragma unroll
        for (int hr = 0; hr < 2; ++hr) {
            int row = wm * 32 + mi * 16 + hr * 8 + trow;
            float m2 = fmaxf(red[row * 2], red[row * 2 + 1]);
            float ls = 0.f;
#pragma unroll
            for (int ni = 0; ni < 8; ++ni) {
                float e0 = fexp(sc[mi][ni][hr * 2 + 0] - m2);
                float e1 = fexp(sc[mi][ni][hr * 2 + 1] - m2);
                sc[mi][ni][hr * 2 + 0] = e0;
                sc[mi][ni][hr * 2 + 1] = e1;
                ls += e0 + e1;
            }
            ls += __shfl_xor_sync(0xffffffffu, ls, 1);
            ls += __shfl_xor_sync(0xffffffffu, ls, 2);
            if ((lane & 3) == 0) red2[row * 2 + wn] = ls;
        }
    __syncthreads();

#pragma unroll
    for (int mi = 0; mi < 2; ++mi)
#pragma unroll
        for (int hr = 0; hr < 2; ++hr) {
            int row = wm * 32 + mi * 16 + hr * 8 + trow;
            inv_[mi][hr] = 1.0f / (red2[row * 2] + red2[row * 2 + 1]);
        }

    // ---- write P (unnormalized exp) as fp16 hi/lo (Q/K region is dead) ----
#pragma unroll
    for (int mi = 0; mi < 2; ++mi)
#pragma unroll
        for (int hr = 0; hr < 2; ++hr) {
            int row = wm * 32 + mi * 16 + hr * 8 + trow;
            uint32_t pb = sb + (uint32_t)(row * AT_PPITCH);
#pragma unroll
            for (int ni = 0; ni < 8; ++ni) {
                float e0 = sc[mi][ni][hr * 2 + 0];
                float e1 = sc[mi][ni][hr * 2 + 1];
                uint32_t hh = h2pk(e0, e1);
                float2 fb = h2unpk(hh);
                uint32_t ll = h2pk(e0 - fb.x, e1 - fb.y);
                int colB = (wn * 64 + ni * 8 + tcol) * 2;
                asm volatile("st.shared.u32 [%0], %1;" :: "r"(pb + AT_PH + colB), "r"(hh) : "memory");
                asm volatile("st.shared.u32 [%0], %1;" :: "r"(pb + AT_PL + colB), "r"(ll) : "memory");
            }
        }
    __syncthreads();

    // ---- PV: O = P * V  (M=128, N=64, K=128), V^T via ldmatrix.trans ----
    float oc[2][4][4];
#pragma unroll
    for (int mi = 0; mi < 2; ++mi)
#pragma unroll
        for (int ni = 0; ni < 4; ++ni)
#pragma unroll
            for (int q = 0; q < 4; ++q) oc[mi][ni][q] = 0.f;

    const int vrow_l = (lane & 7) + ((lane >> 3) & 1) * 8;   // + ks*16
    const int vcol_l = wn * 64 + ((lane >> 4) & 1) * 16;     // bytes; + p*32

#pragma unroll
    for (int ks = 0; ks < 8; ++ks) {
        uint32_t ph[2][4], pl[2][4];
#pragma unroll
        for (int mi = 0; mi < 2; ++mi) {
            uint32_t ad = sb + (uint32_t)((a_row + mi * 16) * AT_PPITCH + ks * 32) + a_off;
            ldsm4(ph[mi], ad + AT_PH);
            ldsm4(pl[mi], ad + AT_PL);
        }
#pragma unroll
        for (int p = 0; p < 2; ++p) {
            uint32_t vh4[4];
            ldsm4t(vh4, sb + (uint32_t)((ks * 16 + vrow_l) * AT_PITCH) + vcol_l + p * 32 + AT_VH);
#pragma unroll
            for (int mi = 0; mi < 2; ++mi) {
#pragma unroll
                for (int half = 0; half < 2; ++half) {
                    float* c4 = oc[mi][p * 2 + half];
                    mma_f16(c4, ph[mi], &vh4[half * 2]);
                    mma_f16(c4, pl[mi], &vh4[half * 2]);
                }
            }
        }
    }

    // ---- epilogue: normalize, split fp16 hi/lo, store ----
#pragma unroll
    for (int mi = 0; mi < 2; ++mi)
#pragma unroll
        for (int hr = 0; hr < 2; ++hr) {
            int row = wm * 32 + mi * 16 + hr * 8 + trow;
            float iv = inv_[mi][hr];
            size_t ob = ((size_t)row * PN + n) * PD + h * PDK;
#pragma unroll
            for (int ni = 0; ni < 4; ++ni) {
                int col = wn * 32 + ni * 8 + tcol;
                float f0 = oc[mi][ni][hr * 2 + 0] * iv;
                float f1 = oc[mi][ni][hr * 2 + 1] * iv;
                uint32_t hh = h2pk(f0, f1);
                float2 fb = h2unpk(hh);
                *(uint32_t*)(Oh + ob + col) = hh;
                *(uint32_t*)(Ol + ob + col) = h2pk(f0 - fb.x, f1 - fb.y);
            }
        }
}

// ---------------------------------------------------------------------------
extern "C" void kernel_launch(void* const* d_in, const int* in_sizes, int n_in,
                              void* d_out, int out_size)
{
    const float* query = (const float*)d_in[0];
    const float* key_i = (const float*)d_in[1];
    const float* value = (const float*)d_in[2];
    const float* Wq = (const float*)d_in[3];
    const float* bq = (const float*)d_in[4];
    const float* Wk = (const float*)d_in[5];
    const float* bk = (const float*)d_in[6];
    const float* Wv = (const float*)d_in[7];
    const float* bv = (const float*)d_in[8];
    const float* Wo = (const float*)d_in[9];
    const float* bo = (const float*)d_in[10];
    float* out = (float*)d_out;

    float *gQ, *gK, *gV;
    cudaGetSymbolAddress((void**)&gQ, g_Q);
    cudaGetSymbolAddress((void**)&gK, g_K);
    cudaGetSymbolAddress((void**)&gV, g_V);
    __half *qh, *ql, *kh, *kl, *vh, *vl, *oh, *ol, *w;
    cudaGetSymbolAddress((void**)&qh, g_qh);
    cudaGetSymbolAddress((void**)&ql, g_ql);
    cudaGetSymbolAddress((void**)&kh, g_kh);
    cudaGetSymbolAddress((void**)&kl, g_kl);
    cudaGetSymbolAddress((void**)&vh, g_vh);
    cudaGetSymbolAddress((void**)&vl, g_vl);
    cudaGetSymbolAddress((void**)&oh, g_oh);
    cudaGetSymbolAddress((void**)&ol, g_ol);
    cudaGetSymbolAddress((void**)&w,  g_w);

    cudaFuncSetAttribute(gemm_f16x2,
                         cudaFuncAttributeMaxDynamicSharedMemorySize, GEMM_SMEM);
    cudaFuncSetAttribute(attn_tc,
                         cudaFuncAttributeMaxDynamicSharedMemorySize, AT_SMEM);

    const int nbig = PM * PD / 4, nw = PD * PD / 4;
    dim3 gg(PD / 256, PM / 128);   // (4, 256)

    split2_f16<<<nbig / 256, 256>>>(query, qh, ql, nbig);
    conv_f16<<<nw / 256, 256>>>(Wq, w + 0 * (size_t)PD * PD, nw);
    split2_f16<<<nbig / 256, 256>>>(key_i, kh, kl, nbig);
    conv_f16<<<nw / 256, 256>>>(Wk, w + 1 * (size_t)PD * PD, nw);
    split2_f16<<<nbig / 256, 256>>>(value, vh, vl, nbig);

    gemm_f16x2<<<gg, 256, GEMM_SMEM>>>(qh, ql, w + 0 * (size_t)PD * PD, bq, gQ);

    conv_f16<<<nw / 256, 256>>>(Wv, w + 2 * (size_t)PD * PD, nw);
    conv_f16<<<nw / 256, 256>>>(Wo, w + 3 * (size_t)PD * PD, nw);

    gemm_f16x2<<<gg, 256, GEMM_SMEM>>>(kh, kl, w + 1 * (size_t)PD * PD, bk, gK);
    gemm_f16x2<<<gg, 256, GEMM_SMEM>>>(vh, vl, w + 2 * (size_t)PD * PD, bv, gV);

    attn_tc<<<PH * PN, 256, AT_SMEM>>>(gQ, gK, gV, oh, ol);

    gemm_f16x2<<<gg, 256, GEMM_SMEM>>>(oh, ol, w + 3 * (size_t)PD * PD, bo, out);
}

// round 11
// speedup vs baseline: 1.1308x; 1.1308x over previous
#include <cuda_runtime.h>
#include <cuda_bf16.h>
#include <cstdint>

// Problem constants
#define PB   128
#define PN   256
#define PD   1024
#define PH   16
#define PDK  64
#define PM   (PB*PN)   // 32768

// ---------------------------------------------------------------------------
// Global scratch (bf16 hi/lo pairs everywhere; no fp32 intermediates)
// ---------------------------------------------------------------------------
__device__ __nv_bfloat16 g_xq_h[PM*PD], g_xq_l[PM*PD];   // input splits
__device__ __nv_bfloat16 g_xk_h[PM*PD], g_xk_l[PM*PD];
__device__ __nv_bfloat16 g_xv_h[PM*PD], g_xv_l[PM*PD];
__device__ __nv_bfloat16 g_pq_h[PM*PD], g_pq_l[PM*PD];   // projection outputs
__device__ __nv_bfloat16 g_pk_h[PM*PD], g_pk_l[PM*PD];
__device__ __nv_bfloat16 g_pv_h[PM*PD], g_pv_l[PM*PD];
__device__ __nv_bfloat16 g_o_h[PM*PD],  g_o_l[PM*PD];    // attention output
__device__ __nv_bfloat16 g_wh[4][PD*PD], g_wl[4][PD*PD]; // weight splits

// ---------------------------------------------------------------------------
// helpers
// ---------------------------------------------------------------------------
__device__ __forceinline__ uint32_t smem_u32(const void* p) {
    uint32_t a;
    asm("{ .reg .u64 t; cvta.to.shared.u64 t, %1; cvt.u32.u64 %0, t; }"
        : "=r"(a) : "l"(p));
    return a;
}
__device__ __forceinline__ uint32_t bf2(float x, float y) {
    uint32_t r;
    asm("cvt.rn.bf16x2.f32 %0, %2, %1;" : "=r"(r) : "f"(x), "f"(y));
    return r;
}
__device__ __forceinline__ void cpa16(uint32_t s, const void* g) {
    asm volatile("cp.async.cg.shared.global [%0], [%1], 16;"
                 :: "r"(s), "l"(g) : "memory");
}
__device__ __forceinline__ void ldsm4(uint32_t* r, uint32_t addr) {
    asm volatile("ldmatrix.sync.aligned.m8n8.x4.shared.b16 {%0,%1,%2,%3}, [%4];"
                 : "=r"(r[0]), "=r"(r[1]), "=r"(r[2]), "=r"(r[3]) : "r"(addr));
}
__device__ __forceinline__ void ldsm4t(uint32_t* r, uint32_t addr) {
    asm volatile("ldmatrix.sync.aligned.m8n8.x4.trans.shared.b16 {%0,%1,%2,%3}, [%4];"
                 : "=r"(r[0]), "=r"(r[1]), "=r"(r[2]), "=r"(r[3]) : "r"(addr));
}
__device__ __forceinline__ void mma_bf16(float* c, const uint32_t* a,
                                         const uint32_t* b) {
    asm volatile("mma.sync.aligned.m16n8k16.row.col.f32.bf16.bf16.f32 "
                 "{%0,%1,%2,%3}, {%4,%5,%6,%7}, {%8,%9}, {%0,%1,%2,%3};"
                 : "+f"(c[0]), "+f"(c[1]), "+f"(c[2]), "+f"(c[3])
                 : "r"(a[0]), "r"(a[1]), "r"(a[2]), "r"(a[3]),
                   "r"(b[0]), "r"(b[1]));
}

// fast exp on FMA/ALU pipes (avoids MUFU rt=8 floor)
__device__ __forceinline__ float fexp(float x) {
    x = fmaxf(x, -80.0f);
    float y = x * 1.44269504089f;
    float t = y + 12582912.0f;
    int   n = __float_as_int(t) - 0x4B400000;
    float fn = t - 12582912.0f;
    float f = y - fn;
    float r = fmaf(f, 1.3333558e-3f, 9.6181291e-3f);
    r = fmaf(f, r, 5.5504108e-2f);
    r = fmaf(f, r, 2.4022650e-1f);
    r = fmaf(f, r, 6.9314718e-1f);
    r = fmaf(f, r, 1.0f);
    float s = __int_as_float((n + 127) << 23);
    return r * s;
}

// ---------------------------------------------------------------------------
// split: fp32 -> bf16 hi + bf16 lo (residual)
// ---------------------------------------------------------------------------
__global__ __launch_bounds__(256)
void split_kernel(const float* __restrict__ src,
                  __nv_bfloat16* __restrict__ hi,
                  __nv_bfloat16* __restrict__ lo, int n4)
{
    int i = blockIdx.x * 256 + threadIdx.x;
    if (i >= n4) return;
    float4 v = ((const float4*)src)[i];
    uint32_t h01 = bf2(v.x, v.y);
    uint32_t h23 = bf2(v.z, v.w);
    float r0 = v.x - __uint_as_float(h01 << 16);
    float r1 = v.y - __uint_as_float(h01 & 0xffff0000u);
    float r2 = v.z - __uint_as_float(h23 << 16);
    float r3 = v.w - __uint_as_float(h23 & 0xffff0000u);
    ((uint2*)hi)[i] = make_uint2(h01, h23);
    ((uint2*)lo)[i] = make_uint2(bf2(r0, r1), bf2(r2, r3));
}

// ---------------------------------------------------------------------------
// GEMM: Y[m,e] = (sum_d A[m,d]*B[e,d] + bias[e]) * scale, 3-term bf16 split.
// CTA tile 128x128, 128 threads (4 warps: 2m x 2n, warp tile 64x64), KC=32,
// 3-stage cp.async pipeline, 32KB/stage -> 96KB smem -> 2 CTAs/SM.
// SPLIT=true: write bf16 hi/lo pair; SPLIT=false: write fp32.
// ---------------------------------------------------------------------------
#define GKC   32
#define GNK   (PD/GKC)          // 32 chunks
#define STGB  32768             // per-stage: Ah 8K | Al 8K | Bh 8K | Bl 8K
#define NSTG  3
#define GEMM_SMEM (NSTG*STGB)   // 96 KB

__device__ __forceinline__ uint32_t sw_off(int r, int c16) {
    return (uint32_t)(r * 64 + ((c16 ^ ((r >> 1) & 3)) << 4));
}

__device__ __forceinline__ void gemm_load_stage(
    uint32_t sbase, int stage, int kk, int tid,
    const __nv_bfloat16* Ah0, const __nv_bfloat16* Al0,
    const __nv_bfloat16* Bh0, const __nv_bfloat16* Bl0)
{
    const uint32_t sb = sbase + (uint32_t)stage * STGB;
    const int koff = kk * GKC;
#pragma unroll
    for (int it = 0; it < 4; ++it) {
        int ch = tid + 128 * it;
        int r = ch >> 2, c = ch & 3;
        const size_t g = (size_t)r * PD + koff + c * 8;
        uint32_t so = sw_off(r, c);
        cpa16(sb + so,         Ah0 + g);
        cpa16(sb +  8192 + so, Al0 + g);
        cpa16(sb + 16384 + so, Bh0 + g);
        cpa16(sb + 24576 + so, Bl0 + g);
    }
    asm volatile("cp.async.commit_group;" ::: "memory");
}

template<bool SPLIT>
__global__ __launch_bounds__(128, 2)
void gemm_bf16x3(const __nv_bfloat16* __restrict__ Ah,
                 const __nv_bfloat16* __restrict__ Al,
                 const __nv_bfloat16* __restrict__ Bh,
                 const __nv_bfloat16* __restrict__ Bl,
                 const float* __restrict__ bias, float scale,
                 float* __restrict__ Yf,
                 __nv_bfloat16* __restrict__ Yh,
                 __nv_bfloat16* __restrict__ Yl)
{
    extern __shared__ char smc[];
    const uint32_t sbase = smem_u32(smc);
    const int tid = threadIdx.x;
    const int wid = tid >> 5, lane = tid & 31;
    const int m0 = blockIdx.y * 128, n0 = blockIdx.x * 128;
    const int wm = wid & 1, wn = wid >> 1;   // 2m x 2n warps, each 64x64

    const __nv_bfloat16* Ah0 = Ah + (size_t)m0 * PD;
    const __nv_bfloat16* Al0 = Al + (size_t)m0 * PD;
    const __nv_bfloat16* Bh0 = Bh + (size_t)n0 * PD;
    const __nv_bfloat16* Bl0 = Bl + (size_t)n0 * PD;

    float acc[4][8][4];
#pragma unroll
    for (int mi = 0; mi < 4; ++mi)
#pragma unroll
        for (int ni = 0; ni < 8; ++ni)
#pragma unroll
            for (int q = 0; q < 4; ++q) acc[mi][ni][q] = 0.f;

    gemm_load_stage(sbase, 0, 0, tid, Ah0, Al0, Bh0, Bl0);
    gemm_load_stage(sbase, 1, 1, tid, Ah0, Al0, Bh0, Bl0);

    const int a_row  = wm * 64 + (lane & 15);
    const int a_c16h = lane >> 4;
    const int b_row  = wn * 64 + ((lane >> 4) << 3) + (lane & 7);
    const int b_c16h = (lane >> 3) & 1;

    for (int kk = 0; kk < GNK; ++kk) {
        if (kk < GNK - 1) asm volatile("cp.async.wait_group 1;" ::: "memory");
        else              asm volatile("cp.async.wait_group 0;" ::: "memory");
        __syncthreads();

        if (kk + 2 < GNK)
            gemm_load_stage(sbase, (kk + 2) % NSTG, kk + 2, tid, Ah0, Al0, Bh0, Bl0);

        const uint32_t sb = sbase + (uint32_t)(kk % NSTG) * STGB;
#pragma unroll
        for (int ks = 0; ks < 2; ++ks) {
            uint32_t ahi[4][4], alo[4][4];
            const int ac = ks * 2 + a_c16h;
#pragma unroll
            for (int mi = 0; mi < 4; ++mi) {
                uint32_t so = sw_off(a_row + mi * 16, ac);
                ldsm4(ahi[mi], sb + so);
                ldsm4(alo[mi], sb + 8192 + so);
            }
            const int bc = ks * 2 + b_c16h;
#pragma unroll
            for (int bi = 0; bi < 4; ++bi) {
                uint32_t bhi[4], blo[4];
                uint32_t so = sw_off(b_row + bi * 16, bc);
                ldsm4(bhi, sb + 16384 + so);
                ldsm4(blo, sb + 24576 + so);
#pragma unroll
                for (int mi = 0; mi < 4; ++mi) {
#pragma unroll
                    for (int half = 0; half < 2; ++half) {
                        float* c4 = acc[mi][bi * 2 + half];
                        mma_bf16(c4, ahi[mi], &bhi[half * 2]);
                        mma_bf16(c4, ahi[mi], &blo[half * 2]);
                        mma_bf16(c4, alo[mi], &bhi[half * 2]);
                    }
                }
            }
        }
    }

    // epilogue: thread t -> rows (t/4, t/4+8), cols (t%4)*2, +1
    const int trow = lane >> 2;
    const int tcol = (lane & 3) * 2;
#pragma unroll
    for (int mi = 0; mi < 4; ++mi) {
#pragma unroll
        for (int rr = 0; rr < 2; ++rr) {
            const int r0 = m0 + wm * 64 + mi * 16 + rr * 8 + trow;
#pragma unroll
            for (int ni = 0; ni < 8; ++ni) {
                const int col = n0 + wn * 64 + ni * 8 + tcol;
                float* c4 = acc[mi][ni];
                float f0 = (c4[rr * 2 + 0] + bias[col])     * scale;
                float f1 = (c4[rr * 2 + 1] + bias[col + 1]) * scale;
                if (SPLIT) {
                    uint32_t hh = bf2(f0, f1);
                    float e0 = f0 - __uint_as_float(hh << 16);
                    float e1 = f1 - __uint_as_float(hh & 0xffff0000u);
                    *(uint32_t*)(Yh + (size_t)r0 * PD + col) = hh;
                    *(uint32_t*)(Yl + (size_t)r0 * PD + col) = bf2(e0, e1);
                } else {
                    *(float2*)(Yf + (size_t)r0 * PD + col) = make_float2(f0, f1);
                }
            }
        }
    }
}

// ---------------------------------------------------------------------------
// Tensor-core attention: one CTA per (h,n), 256 threads (8 warps: 4m x 2n).
// Inputs arrive pre-split bf16 hi/lo (Q pre-scaled by 1/8 in its GEMM).
// Scores 128x128x64 (3-term), softmax (fexp), PV 128x64x128 via
// ldmatrix.trans. Writes bf16 hi/lo output split.
// ---------------------------------------------------------------------------
#define AT_PITCH   144           // rows: 64 bf16 = 128B + 16 pad
#define AT_PPITCH  272           // P rows: 128 bf16 = 256B + 16 pad
#define AT_QH      0
#define AT_QL      18432
#define AT_KH      36864
#define AT_KL      55296
#define AT_VH      73728
#define AT_VL      92160
#define AT_RED     110592
#define AT_RED2    111616
#define AT_SMEM    112640
#define AT_PH      0             // P reuses dead Q/K region
#define AT_PL      34816

__global__ __launch_bounds__(256)
void attn_tc(const __nv_bfloat16* __restrict__ Qh, const __nv_bfloat16* __restrict__ Ql,
             const __nv_bfloat16* __restrict__ Kh, const __nv_bfloat16* __restrict__ Kl,
             const __nv_bfloat16* __restrict__ Vh, const __nv_bfloat16* __restrict__ Vl,
             __nv_bfloat16* __restrict__ Oh, __nv_bfloat16* __restrict__ Ol)
{
    extern __shared__ char sm[];
    const uint32_t sb = smem_u32(sm);
    const int tid = threadIdx.x;
    const int wid = tid >> 5, lane = tid & 31;
    const int wm = wid & 3, wn = wid >> 2;   // 4m x 2n
    const int hn = blockIdx.x;
    const int h  = hn >> 8;
    const int n  = hn & 255;
    const size_t rowoff = (size_t)n * PD + h * PDK;

    // ---- gather pre-split bf16 tiles: 6 halves, 1024 16B-chunks each ----
#define AT_LOADHALF(SRC, BASE)                                              \
    {                                                                       \
        _Pragma("unroll")                                                   \
        for (int j = 0; j < 4; ++j) {                                       \
            int i = tid + 256 * j;                                          \
            int r = i >> 3, c = i & 7;                                      \
            uint4 v = *(const uint4*)((SRC) + (size_t)r * (PD * PN)         \
                                      + rowoff + c * 8);                    \
            *(uint4*)(sm + (BASE) + r * AT_PITCH + c * 16) = v;             \
        }                                                                   \
    }
    AT_LOADHALF(Qh, AT_QH)
    AT_LOADHALF(Ql, AT_QL)
    AT_LOADHALF(Kh, AT_KH)
    AT_LOADHALF(Kl, AT_KL)
    AT_LOADHALF(Vh, AT_VH)
    AT_LOADHALF(Vl, AT_VL)
#undef AT_LOADHALF
    __syncthreads();

    // ---- scores: S = Qs * K^T  (M=128, N=128, K=64), 3-term ----
    float sc[2][8][4];
#pragma unroll
    for (int mi = 0; mi < 2; ++mi)
#pragma unroll
        for (int ni = 0; ni < 8; ++ni)
#pragma unroll
            for (int q = 0; q < 4; ++q) sc[mi][ni][q] = 0.f;

    const int a_row = wm * 32 + (lane & 15);
    const int a_off = (lane >> 4) * 16;                          // bytes
    const int b_row = wn * 64 + ((lane >> 4) << 3) + (lane & 7);
    const int b_off = ((lane >> 3) & 1) * 16;                    // bytes

#pragma unroll
    for (int ks = 0; ks < 4; ++ks) {
        uint32_t ah[2][4], al[2][4];
#pragma unroll
        for (int mi = 0; mi < 2; ++mi) {
            uint32_t ad = sb + (uint32_t)((a_row + mi * 16) * AT_PITCH + ks * 32) + a_off;
            ldsm4(ah[mi], ad + AT_QH);
            ldsm4(al[mi], ad + AT_QL);
        }
#pragma unroll
        for (int bi = 0; bi < 4; ++bi) {
            uint32_t bh[4], bl[4];
            uint32_t bd = sb + (uint32_t)((b_row + bi * 16) * AT_PITCH + ks * 32) + b_off;
            ldsm4(bh, bd + AT_KH);
            ldsm4(bl, bd + AT_KL);
#pragma unroll
            for (int mi = 0; mi < 2; ++mi) {
#pragma unroll
                for (int half = 0; half < 2; ++half) {
                    float* c4 = sc[mi][bi * 2 + half];
                    mma_bf16(c4, ah[mi], &bh[half * 2]);
                    mma_bf16(c4, ah[mi], &bl[half * 2]);
                    mma_bf16(c4, al[mi], &bh[half * 2]);
                }
            }
        }
    }

    // ---- softmax over rows ----
    const int trow = lane >> 2;
    const int tcol = (lane & 3) * 2;
    float* red  = (float*)(sm + AT_RED);
    float* red2 = (float*)(sm + AT_RED2);

#pragma unroll
    for (int mi = 0; mi < 2; ++mi)
#pragma unroll
        for (int hr = 0; hr < 2; ++hr) {
            float m = -1e30f;
#pragma unroll
            for (int ni = 0; ni < 8; ++ni) {
                m = fmaxf(m, sc[mi][ni][hr * 2 + 0]);
                m = fmaxf(m, sc[mi][ni][hr * 2 + 1]);
            }
            m = fmaxf(m, __shfl_xor_sync(0xffffffffu, m, 1));
            m = fmaxf(m, __shfl_xor_sync(0xffffffffu, m, 2));
            int row = wm * 32 + mi * 16 + hr * 8 + trow;
            if ((lane & 3) == 0) red[row * 2 + wn] = m;
        }
    __syncthreads();

    float inv_[2][2];
#pragma unroll
    for (int mi = 0; mi < 2; ++mi)
#pragma unroll
        for (int hr = 0; hr < 2; ++hr) {
            int row = wm * 32 + mi * 16 + hr * 8 + trow;
            float m2 = fmaxf(red[row * 2], red[row * 2 + 1]);
            float ls = 0.f;
#pragma unroll
            for (int ni = 0; ni < 8; ++ni) {
                float e0 = fexp(sc[mi][ni][hr * 2 + 0] - m2);
                float e1 = fexp(sc[mi][ni][hr * 2 + 1] - m2);
                sc[mi][ni][hr * 2 + 0] = e0;
                sc[mi][ni][hr * 2 + 1] = e1;
                ls += e0 + e1;
            }
            ls += __shfl_xor_sync(0xffffffffu, ls, 1);
            ls += __shfl_xor_sync(0xffffffffu, ls, 2);
            if ((lane & 3) == 0) red2[row * 2 + wn] = ls;
        }
    __syncthreads();

#pragma unroll
    for (int mi = 0; mi < 2; ++mi)
#pragma unroll
        for (int hr = 0; hr < 2; ++hr) {
            int row = wm * 32 + mi * 16 + hr * 8 + trow;
            inv_[mi][hr] = 1.0f / (red2[row * 2] + red2[row * 2 + 1]);
        }

    // ---- write P (unnormalized exp) as bf16 hi/lo ----
#pragma unroll
    for (int mi = 0; mi < 2; ++mi)
#pragma unroll
        for (int hr = 0; hr < 2; ++hr) {
            int row = wm * 32 + mi * 16 + hr * 8 + trow;
            uint32_t pb = sb + (uint32_t)(row * AT_PPITCH);
#pragma unroll
            for (int ni = 0; ni < 8; ++ni) {
                float e0 = sc[mi][ni][hr * 2 + 0];
                float e1 = sc[mi][ni][hr * 2 + 1];
                uint32_t hh = bf2(e0, e1);
                float r0 = e0 - __uint_as_float(hh << 16);
                float r1 = e1 - __uint_as_float(hh & 0xffff0000u);
                uint32_t ll = bf2(r0, r1);
                int colB = (wn * 64 + ni * 8 + tcol) * 2;
                asm volatile("st.shared.u32 [%0], %1;" :: "r"(pb + AT_PH + colB), "r"(hh) : "memory");
                asm volatile("st.shared.u32 [%0], %1;" :: "r"(pb + AT_PL + colB), "r"(ll) : "memory");
            }
        }
    __syncthreads();

    // ---- PV: O = P * V  (M=128, N=64, K=128), V^T via ldmatrix.trans ----
    float oc[2][4][4];
#pragma unroll
    for (int mi = 0; mi < 2; ++mi)
#pragma unroll
        for (int ni = 0; ni < 4; ++ni)
#pragma unroll
            for (int q = 0; q < 4; ++q) oc[mi][ni][q] = 0.f;

    const int vrow_l = (lane & 7) + ((lane >> 3) & 1) * 8;   // + ks*16
    const int vcol_l = wn * 64 + ((lane >> 4) & 1) * 16;     // bytes; + p*32

#pragma unroll
    for (int ks = 0; ks < 8; ++ks) {
        uint32_t ph[2][4], pl[2][4];
#pragma unroll
        for (int mi = 0; mi < 2; ++mi) {
            uint32_t ad = sb + (uint32_t)((a_row + mi * 16) * AT_PPITCH + ks * 32) + a_off;
            ldsm4(ph[mi], ad + AT_PH);
            ldsm4(pl[mi], ad + AT_PL);
        }
#pragma unroll
        for (int p = 0; p < 2; ++p) {
            uint32_t vh4[4], vl4[4];
            uint32_t vd = sb + (uint32_t)((ks * 16 + vrow_l) * AT_PITCH) + vcol_l + p * 32;
            ldsm4t(vh4, vd + AT_VH);
            ldsm4t(vl4, vd + AT_VL);
#pragma unroll
            for (int mi = 0; mi < 2; ++mi) {
#pragma unroll
                for (int half = 0; half < 2; ++half) {
                    float* c4 = oc[mi][p * 2 + half];
                    mma_bf16(c4, ph[mi], &vh4[half * 2]);
                    mma_bf16(c4, ph[mi], &vl4[half * 2]);
                    mma_bf16(c4, pl[mi], &vh4[half * 2]);
                }
            }
        }
    }

    // ---- epilogue: normalize, split to bf16 hi/lo, store ----
#pragma unroll
    for (int mi = 0; mi < 2; ++mi)
#pragma unroll
        for (int hr = 0; hr < 2; ++hr) {
            int row = wm * 32 + mi * 16 + hr * 8 + trow;
            float iv = inv_[mi][hr];
            size_t ob = ((size_t)row * PN + n) * PD + h * PDK;
#pragma unroll
            for (int ni = 0; ni < 4; ++ni) {
                int col = wn * 32 + ni * 8 + tcol;
                float f0 = oc[mi][ni][hr * 2 + 0] * iv;
                float f1 = oc[mi][ni][hr * 2 + 1] * iv;
                uint32_t hh = bf2(f0, f1);
                float r0 = f0 - __uint_as_float(hh << 16);
                float r1 = f1 - __uint_as_float(hh & 0xffff0000u);
                *(uint32_t*)(Oh + ob + col) = hh;
                *(uint32_t*)(Ol + ob + col) = bf2(r0, r1);
            }
        }
}

// ---------------------------------------------------------------------------
extern "C" void kernel_launch(void* const* d_in, const int* in_sizes, int n_in,
                              void* d_out, int out_size)
{
    const float* query = (const float*)d_in[0];
    const float* key_i = (const float*)d_in[1];
    const float* value = (const float*)d_in[2];
    const float* Wq = (const float*)d_in[3];
    const float* bq = (const float*)d_in[4];
    const float* Wk = (const float*)d_in[5];
    const float* bk = (const float*)d_in[6];
    const float* Wv = (const float*)d_in[7];
    const float* bv = (const float*)d_in[8];
    const float* Wo = (const float*)d_in[9];
    const float* bo = (const float*)d_in[10];
    float* out = (float*)d_out;

    __nv_bfloat16 *xqh, *xql, *xkh, *xkl, *xvh, *xvl;
    __nv_bfloat16 *pqh, *pql, *pkh, *pkl, *pvh, *pvl, *ohp, *olp, *wh, *wl;
    cudaGetSymbolAddress((void**)&xqh, g_xq_h);
    cudaGetSymbolAddress((void**)&xql, g_xq_l);
    cudaGetSymbolAddress((void**)&xkh, g_xk_h);
    cudaGetSymbolAddress((void**)&xkl, g_xk_l);
    cudaGetSymbolAddress((void**)&xvh, g_xv_h);
    cudaGetSymbolAddress((void**)&xvl, g_xv_l);
    cudaGetSymbolAddress((void**)&pqh, g_pq_h);
    cudaGetSymbolAddress((void**)&pql, g_pq_l);
    cudaGetSymbolAddress((void**)&pkh, g_pk_h);
    cudaGetSymbolAddress((void**)&pkl, g_pk_l);
    cudaGetSymbolAddress((void**)&pvh, g_pv_h);
    cudaGetSymbolAddress((void**)&pvl, g_pv_l);
    cudaGetSymbolAddress((void**)&ohp, g_o_h);
    cudaGetSymbolAddress((void**)&olp, g_o_l);
    cudaGetSymbolAddress((void**)&wh,  g_wh);
    cudaGetSymbolAddress((void**)&wl,  g_wl);

    cudaFuncSetAttribute(gemm_bf16x3<true>,
                         cudaFuncAttributeMaxDynamicSharedMemorySize, GEMM_SMEM);
    cudaFuncSetAttribute(gemm_bf16x3<false>,
                         cudaFuncAttributeMaxDynamicSharedMemorySize, GEMM_SMEM);
    cudaFuncSetAttribute(attn_tc,
                         cudaFuncAttributeMaxDynamicSharedMemorySize, AT_SMEM);

    const int nbig = PM * PD / 4, nw = PD * PD / 4;
    dim3 gg(PD / 128, PM / 128);   // (8, 256)

    split_kernel<<<nbig / 256, 256>>>(query, xqh, xql, nbig);
    split_kernel<<<nw / 256, 256>>>(Wq, wh + 0 * (size_t)PD * PD, wl + 0 * (size_t)PD * PD, nw);
    split_kernel<<<nbig / 256, 256>>>(key_i, xkh, xkl, nbig);
    split_kernel<<<nw / 256, 256>>>(Wk, wh + 1 * (size_t)PD * PD, wl + 1 * (size_t)PD * PD, nw);
    split_kernel<<<nbig / 256, 256>>>(value, xvh, xvl, nbig);

    gemm_bf16x3<true><<<gg, 128, GEMM_SMEM>>>(
        xqh, xql, wh + 0 * (size_t)PD * PD, wl + 0 * (size_t)PD * PD,
        bq, 0.125f, nullptr, pqh, pql);

    split_kernel<<<nw / 256, 256>>>(Wv, wh + 2 * (size_t)PD * PD, wl + 2 * (size_t)PD * PD, nw);
    split_kernel<<<nw / 256, 256>>>(Wo, wh + 3 * (size_t)PD * PD, wl + 3 * (size_t)PD * PD, nw);

    gemm_bf16x3<true><<<gg, 128, GEMM_SMEM>>>(
        xkh, xkl, wh + 1 * (size_t)PD * PD, wl + 1 * (size_t)PD * PD,
        bk, 1.0f, nullptr, pkh, pkl);
    gemm_bf16x3<true><<<gg, 128, GEMM_SMEM>>>(
        xvh, xvl, wh + 2 * (size_t)PD * PD, wl + 2 * (size_t)PD * PD,
        bv, 1.0f, nullptr, pvh, pvl);

    attn_tc<<<PH * PN, 256, AT_SMEM>>>(pqh, pql, pkh, pkl, pvh, pvl, ohp, olp);

    gemm_bf16x3<false><<<gg, 128, GEMM_SMEM>>>(
        ohp, olp, wh + 3 * (size_t)PD * PD, wl + 3 * (size_t)PD * PD,
        bo, 1.0f, out, nullptr, nullptr);
}

// round 13
// speedup vs baseline: 1.1324x; 1.0014x over previous
#include <cuda_runtime.h>
#include <cuda_bf16.h>
#include <cstdint>

// Problem constants
#define PB   128
#define PN   256
#define PD   1024
#define PH   16
#define PDK  64
#define PM   (PB*PN)   // 32768

// ---------------------------------------------------------------------------
// Global scratch (bf16 hi/lo pairs everywhere; no fp32 intermediates)
// ---------------------------------------------------------------------------
__device__ __nv_bfloat16 g_xq_h[PM*PD], g_xq_l[PM*PD];   // input splits
__device__ __nv_bfloat16 g_xk_h[PM*PD], g_xk_l[PM*PD];
__device__ __nv_bfloat16 g_xv_h[PM*PD], g_xv_l[PM*PD];
__device__ __nv_bfloat16 g_pq_h[PM*PD], g_pq_l[PM*PD];   // projection outputs
__device__ __nv_bfloat16 g_pk_h[PM*PD], g_pk_l[PM*PD];
__device__ __nv_bfloat16 g_pv_h[PM*PD], g_pv_l[PM*PD];
__device__ __nv_bfloat16 g_o_h[PM*PD],  g_o_l[PM*PD];    // attention output
__device__ __nv_bfloat16 g_wh[4][PD*PD], g_wl[4][PD*PD]; // weight splits

// ---------------------------------------------------------------------------
// helpers
// ---------------------------------------------------------------------------
__device__ __forceinline__ uint32_t smem_u32(const void* p) {
    uint32_t a;
    asm("{ .reg .u64 t; cvta.to.shared.u64 t, %1; cvt.u32.u64 %0, t; }"
        : "=r"(a) : "l"(p));
    return a;
}
__device__ __forceinline__ uint32_t bf2(float x, float y) {
    uint32_t r;
    asm("cvt.rn.bf16x2.f32 %0, %2, %1;" : "=r"(r) : "f"(x), "f"(y));
    return r;
}
__device__ __forceinline__ void cpa16(uint32_t s, const void* g) {
    asm volatile("cp.async.cg.shared.global [%0], [%1], 16;"
                 :: "r"(s), "l"(g) : "memory");
}
__device__ __forceinline__ void ldsm4(uint32_t* r, uint32_t addr) {
    asm volatile("ldmatrix.sync.aligned.m8n8.x4.shared.b16 {%0,%1,%2,%3}, [%4];"
                 : "=r"(r[0]), "=r"(r[1]), "=r"(r[2]), "=r"(r[3]) : "r"(addr));
}
__device__ __forceinline__ void ldsm4t(uint32_t* r, uint32_t addr) {
    asm volatile("ldmatrix.sync.aligned.m8n8.x4.trans.shared.b16 {%0,%1,%2,%3}, [%4];"
                 : "=r"(r[0]), "=r"(r[1]), "=r"(r[2]), "=r"(r[3]) : "r"(addr));
}
__device__ __forceinline__ void mma_bf16(float* c, const uint32_t* a,
                                         const uint32_t* b) {
    asm volatile("mma.sync.aligned.m16n8k16.row.col.f32.bf16.bf16.f32 "
                 "{%0,%1,%2,%3}, {%4,%5,%6,%7}, {%8,%9}, {%0,%1,%2,%3};"
                 : "+f"(c[0]), "+f"(c[1]), "+f"(c[2]), "+f"(c[3])
                 : "r"(a[0]), "r"(a[1]), "r"(a[2]), "r"(a[3]),
                   "r"(b[0]), "r"(b[1]));
}

// fast exp on FMA/ALU pipes (avoids MUFU rt=8 floor)
__device__ __forceinline__ float fexp(float x) {
    x = fmaxf(x, -80.0f);
    float y = x * 1.44269504089f;
    float t = y + 12582912.0f;
    int   n = __float_as_int(t) - 0x4B400000;
    float fn = t - 12582912.0f;
    float f = y - fn;
    float r = fmaf(f, 1.3333558e-3f, 9.6181291e-3f);
    r = fmaf(f, r, 5.5504108e-2f);
    r = fmaf(f, r, 2.4022650e-1f);
    r = fmaf(f, r, 6.9314718e-1f);
    r = fmaf(f, r, 1.0f);
    float s = __int_as_float((n + 127) << 23);
    return r * s;
}

// ---------------------------------------------------------------------------
// split: fp32 -> bf16 hi + bf16 lo (residual). 4 float4 per thread, loads
// batched up front (MLP=4 hides DRAM latency).
// ---------------------------------------------------------------------------
__global__ __launch_bounds__(256)
void split_kernel(const float* __restrict__ src,
                  __nv_bfloat16* __restrict__ hi,
                  __nv_bfloat16* __restrict__ lo, int n4)
{
    const int stride = gridDim.x * 256;
    const int i0 = blockIdx.x * 256 + threadIdx.x;
    float4 v[4];
#pragma unroll
    for (int j = 0; j < 4; ++j) v[j] = ((const float4*)src)[i0 + j * stride];
#pragma unroll
    for (int j = 0; j < 4; ++j) {
        int i = i0 + j * stride;
        uint32_t h01 = bf2(v[j].x, v[j].y);
        uint32_t h23 = bf2(v[j].z, v[j].w);
        float r0 = v[j].x - __uint_as_float(h01 << 16);
        float r1 = v[j].y - __uint_as_float(h01 & 0xffff0000u);
        float r2 = v[j].z - __uint_as_float(h23 << 16);
        float r3 = v[j].w - __uint_as_float(h23 & 0xffff0000u);
        ((uint2*)hi)[i] = make_uint2(h01, h23);
        ((uint2*)lo)[i] = make_uint2(bf2(r0, r1), bf2(r2, r3));
    }
}

// ---------------------------------------------------------------------------
// GEMM: Y[m,e] = (sum_d A[m,d]*B[e,d] + bias[e]) * scale, 3-term bf16 split.
// CTA tile 128x128, 128 threads (4 warps: 2m x 2n, warp tile 64x64), KC=32,
// 3-stage cp.async pipeline, 32KB/stage -> 96KB smem -> 2 CTAs/SM.
// Inner loop: ALL 16 LDSM issued up front per ks, then 24-MMA burst.
// ---------------------------------------------------------------------------
#define GKC   32
#define GNK   (PD/GKC)          // 32 chunks
#define STGB  32768             // per-stage: Ah 8K | Al 8K | Bh 8K | Bl 8K
#define NSTG  3
#define GEMM_SMEM (NSTG*STGB)   // 96 KB

__device__ __forceinline__ uint32_t sw_off(int r, int c16) {
    return (uint32_t)(r * 64 + ((c16 ^ ((r >> 1) & 3)) << 4));
}

__device__ __forceinline__ void gemm_load_stage(
    uint32_t sbase, int stage, int kk, int tid,
    const __nv_bfloat16* Ah0, const __nv_bfloat16* Al0,
    const __nv_bfloat16* Bh0, const __nv_bfloat16* Bl0)
{
    const uint32_t sb = sbase + (uint32_t)stage * STGB;
    const int koff = kk * GKC;
#pragma unroll
    for (int it = 0; it < 4; ++it) {
        int ch = tid + 128 * it;
        int r = ch >> 2, c = ch & 3;
        const size_t g = (size_t)r * PD + koff + c * 8;
        uint32_t so = sw_off(r, c);
        cpa16(sb + so,         Ah0 + g);
        cpa16(sb +  8192 + so, Al0 + g);
        cpa16(sb + 16384 + so, Bh0 + g);
        cpa16(sb + 24576 + so, Bl0 + g);
    }
    asm volatile("cp.async.commit_group;" ::: "memory");
}

template<bool SPLIT>
__global__ __launch_bounds__(128, 2)
void gemm_bf16x3(const __nv_bfloat16* __restrict__ Ah,
                 const __nv_bfloat16* __restrict__ Al,
                 const __nv_bfloat16* __restrict__ Bh,
                 const __nv_bfloat16* __restrict__ Bl,
                 const float* __restrict__ bias, float scale,
                 float* __restrict__ Yf,
                 __nv_bfloat16* __restrict__ Yh,
                 __nv_bfloat16* __restrict__ Yl)
{
    extern __shared__ char smc[];
    const uint32_t sbase = smem_u32(smc);
    const int tid = threadIdx.x;
    const int wid = tid >> 5, lane = tid & 31;
    const int m0 = blockIdx.y * 128, n0 = blockIdx.x * 128;
    const int wm = wid & 1, wn = wid >> 1;   // 2m x 2n warps, each 64x64

    const __nv_bfloat16* Ah0 = Ah + (size_t)m0 * PD;
    const __nv_bfloat16* Al0 = Al + (size_t)m0 * PD;
    const __nv_bfloat16* Bh0 = Bh + (size_t)n0 * PD;
    const __nv_bfloat16* Bl0 = Bl + (size_t)n0 * PD;

    float acc[4][8][4];
#pragma unroll
    for (int mi = 0; mi < 4; ++mi)
#pragma unroll
        for (int ni = 0; ni < 8; ++ni)
#pragma unroll
            for (int q = 0; q < 4; ++q) acc[mi][ni][q] = 0.f;

    gemm_load_stage(sbase, 0, 0, tid, Ah0, Al0, Bh0, Bl0);
    gemm_load_stage(sbase, 1, 1, tid, Ah0, Al0, Bh0, Bl0);

    const int a_row  = wm * 64 + (lane & 15);
    const int a_c16h = lane >> 4;
    const int b_row  = wn * 64 + ((lane >> 4) << 3) + (lane & 7);
    const int b_c16h = (lane >> 3) & 1;

    for (int kk = 0; kk < GNK; ++kk) {
        if (kk < GNK - 1) asm volatile("cp.async.wait_group 1;" ::: "memory");
        else              asm volatile("cp.async.wait_group 0;" ::: "memory");
        __syncthreads();

        if (kk + 2 < GNK)
            gemm_load_stage(sbase, (kk + 2) % NSTG, kk + 2, tid, Ah0, Al0, Bh0, Bl0);

        const uint32_t sb = sbase + (uint32_t)(kk % NSTG) * STGB;
#pragma unroll
        for (int ks = 0; ks < 2; ++ks) {
            uint32_t ahi[4][4], alo[4][4], bhi[4][4], blo[4][4];
            const int ac = ks * 2 + a_c16h;
            const int bc = ks * 2 + b_c16h;
            // all 16 LDSM up front: back-to-back issue hides LDS latency
#pragma unroll
            for (int mi = 0; mi < 4; ++mi) {
                uint32_t so = sw_off(a_row + mi * 16, ac);
                ldsm4(ahi[mi], sb + so);
                ldsm4(alo[mi], sb + 8192 + so);
            }
#pragma unroll
            for (int bi = 0; bi < 4; ++bi) {
                uint32_t so = sw_off(b_row + bi * 16, bc);
                ldsm4(bhi[bi], sb + 16384 + so);
                ldsm4(blo[bi], sb + 24576 + so);
            }
            // 96-MMA burst
#pragma unroll
            for (int bi = 0; bi < 4; ++bi)
#pragma unroll
                for (int mi = 0; mi < 4; ++mi)
#pragma unroll
                    for (int half = 0; half < 2; ++half) {
                        float* c4 = acc[mi][bi * 2 + half];
                        mma_bf16(c4, ahi[mi], &bhi[bi][half * 2]);
                        mma_bf16(c4, ahi[mi], &blo[bi][half * 2]);
                        mma_bf16(c4, alo[mi], &bhi[bi][half * 2]);
                    }
        }
    }

    // epilogue: thread t -> rows (t/4, t/4+8), cols (t%4)*2, +1
    const int trow = lane >> 2;
    const int tcol = (lane & 3) * 2;
#pragma unroll
    for (int mi = 0; mi < 4; ++mi) {
#pragma unroll
        for (int rr = 0; rr < 2; ++rr) {
            const int r0 = m0 + wm * 64 + mi * 16 + rr * 8 + trow;
#pragma unroll
            for (int ni = 0; ni < 8; ++ni) {
                const int col = n0 + wn * 64 + ni * 8 + tcol;
                float* c4 = acc[mi][ni];
                float f0 = (c4[rr * 2 + 0] + bias[col])     * scale;
                float f1 = (c4[rr * 2 + 1] + bias[col + 1]) * scale;
                if (SPLIT) {
                    uint32_t hh = bf2(f0, f1);
                    float e0 = f0 - __uint_as_float(hh << 16);
                    float e1 = f1 - __uint_as_float(hh & 0xffff0000u);
                    *(uint32_t*)(Yh + (size_t)r0 * PD + col) = hh;
                    *(uint32_t*)(Yl + (size_t)r0 * PD + col) = bf2(e0, e1);
                } else {
                    *(float2*)(Yf + (size_t)r0 * PD + col) = make_float2(f0, f1);
                }
            }
        }
    }
}

// ---------------------------------------------------------------------------
// Tensor-core attention: one CTA per (h,n), 256 threads (8 warps: 4m x 2n).
// Inputs arrive pre-split bf16 hi/lo (Q pre-scaled by 1/8 in its GEMM).
// ---------------------------------------------------------------------------
#define AT_PITCH   144           // rows: 64 bf16 = 128B + 16 pad
#define AT_PPITCH  272           // P rows: 128 bf16 = 256B + 16 pad
#define AT_QH      0
#define AT_QL      18432
#define AT_KH      36864
#define AT_KL      55296
#define AT_VH      73728
#define AT_VL      92160
#define AT_RED     110592
#define AT_RED2    111616
#define AT_SMEM    112640
#define AT_PH      0             // P reuses dead Q/K region
#define AT_PL      34816

__global__ __launch_bounds__(256)
void attn_tc(const __nv_bfloat16* __restrict__ Qh, const __nv_bfloat16* __restrict__ Ql,
             const __nv_bfloat16* __restrict__ Kh, const __nv_bfloat16* __restrict__ Kl,
             const __nv_bfloat16* __restrict__ Vh, const __nv_bfloat16* __restrict__ Vl,
             __nv_bfloat16* __restrict__ Oh, __nv_bfloat16* __restrict__ Ol)
{
    extern __shared__ char sm[];
    const uint32_t sb = smem_u32(sm);
    const int tid = threadIdx.x;
    const int wid = tid >> 5, lane = tid & 31;
    const int wm = wid & 3, wn = wid >> 2;   // 4m x 2n
    const int hn = blockIdx.x;
    const int h  = hn >> 8;
    const int n  = hn & 255;
    const size_t rowoff = (size_t)n * PD + h * PDK;

    // ---- gather pre-split bf16 tiles ----
#define AT_LOADHALF(SRC, BASE)                                              \
    {                                                                       \
        _Pragma("unroll")                                                   \
        for (int j = 0; j < 4; ++j) {                                       \
            int i = tid + 256 * j;                                          \
            int r = i >> 3, c = i & 7;                                      \
            uint4 v = *(const uint4*)((SRC) + (size_t)r * (PD * PN)         \
                                      + rowoff + c * 8);                    \
            *(uint4*)(sm + (BASE) + r * AT_PITCH + c * 16) = v;             \
        }                                                                   \
    }
    AT_LOADHALF(Qh, AT_QH)
    AT_LOADHALF(Ql, AT_QL)
    AT_LOADHALF(Kh, AT_KH)
    AT_LOADHALF(Kl, AT_KL)
    AT_LOADHALF(Vh, AT_VH)
    AT_LOADHALF(Vl, AT_VL)
#undef AT_LOADHALF
    __syncthreads();

    // ---- scores: S = Qs * K^T  (M=128, N=128, K=64), 3-term ----
    float sc[2][8][4];
#pragma unroll
    for (int mi = 0; mi < 2; ++mi)
#pragma unroll
        for (int ni = 0; ni < 8; ++ni)
#pragma unroll
            for (int q = 0; q < 4; ++q) sc[mi][ni][q] = 0.f;

    const int a_row = wm * 32 + (lane & 15);
    const int a_off = (lane >> 4) * 16;                          // bytes
    const int b_row = wn * 64 + ((lane >> 4) << 3) + (lane & 7);
    const int b_off = ((lane >> 3) & 1) * 16;                    // bytes

#pragma unroll
    for (int ks = 0; ks < 4; ++ks) {
        uint32_t ah[2][4], al[2][4];
#pragma unroll
        for (int mi = 0; mi < 2; ++mi) {
            uint32_t ad = sb + (uint32_t)((a_row + mi * 16) * AT_PITCH + ks * 32) + a_off;
            ldsm4(ah[mi], ad + AT_QH);
            ldsm4(al[mi], ad + AT_QL);
        }
#pragma unroll
        for (int bi = 0; bi < 4; ++bi) {
            uint32_t bh[4], bl[4];
            uint32_t bd = sb + (uint32_t)((b_row + bi * 16) * AT_PITCH + ks * 32) + b_off;
            ldsm4(bh, bd + AT_KH);
            ldsm4(bl, bd + AT_KL);
#pragma unroll
            for (int mi = 0; mi < 2; ++mi) {
#pragma unroll
                for (int half = 0; half < 2; ++half) {
                    float* c4 = sc[mi][bi * 2 + half];
                    mma_bf16(c4, ah[mi], &bh[half * 2]);
                    mma_bf16(c4, ah[mi], &bl[half * 2]);
                    mma_bf16(c4, al[mi], &bh[half * 2]);
                }
            }
        }
    }

    // ---- softmax over rows ----
    const int trow = lane >> 2;
    const int tcol = (lane & 3) * 2;
    float* red  = (float*)(sm + AT_RED);
    float* red2 = (float*)(sm + AT_RED2);

#pragma unroll
    for (int mi = 0; mi < 2; ++mi)
#pragma unroll
        for (int hr = 0; hr < 2; ++hr) {
            float m = -1e30f;
#pragma unroll
            for (int ni = 0; ni < 8; ++ni) {
                m = fmaxf(m, sc[mi][ni][hr * 2 + 0]);
                m = fmaxf(m, sc[mi][ni][hr * 2 + 1]);
            }
            m = fmaxf(m, __shfl_xor_sync(0xffffffffu, m, 1));
            m = fmaxf(m, __shfl_xor_sync(0xffffffffu, m, 2));
            int row = wm * 32 + mi * 16 + hr * 8 + trow;
            if ((lane & 3) == 0) red[row * 2 + wn] = m;
        }
    __syncthreads();

    float inv_[2][2];
#pragma unroll
    for (int mi = 0; mi < 2; ++mi)
#pragma unroll
        for (int hr = 0; hr < 2; ++hr) {
            int row = wm * 32 + mi * 16 + hr * 8 + trow;
            float m2 = fmaxf(red[row * 2], red[row * 2 + 1]);
            float ls = 0.f;
#pragma unroll
            for (int ni = 0; ni < 8; ++ni) {
                float e0 = fexp(sc[mi][ni][hr * 2 + 0] - m2);
                float e1 = fexp(sc[mi][ni][hr * 2 + 1] - m2);
                sc[mi][ni][hr * 2 + 0] = e0;
                sc[mi][ni][hr * 2 + 1] = e1;
                ls += e0 + e1;
            }
            ls += __shfl_xor_sync(0xffffffffu, ls, 1);
            ls += __shfl_xor_sync(0xffffffffu, ls, 2);
            if ((lane & 3) == 0) red2[row * 2 + wn] = ls;
        }
    __syncthreads();

#pragma unroll
    for (int mi = 0; mi < 2; ++mi)
#pragma unroll
        for (int hr = 0; hr < 2; ++hr) {
            int row = wm * 32 + mi * 16 + hr * 8 + trow;
            inv_[mi][hr] = 1.0f / (red2[row * 2] + red2[row * 2 + 1]);
        }

    // ---- write P (unnormalized exp) as bf16 hi/lo ----
#pragma unroll
    for (int mi = 0; mi < 2; ++mi)
#pragma unroll
        for (int hr = 0; hr < 2; ++hr) {
            int row = wm * 32 + mi * 16 + hr * 8 + trow;
            uint32_t pb = sb + (uint32_t)(row * AT_PPITCH);
#pragma unroll
            for (int ni = 0; ni < 8; ++ni) {
                float e0 = sc[mi][ni][hr * 2 + 0];
                float e1 = sc[mi][ni][hr * 2 + 1];
                uint32_t hh = bf2(e0, e1);
                float r0 = e0 - __uint_as_float(hh << 16);
                float r1 = e1 - __uint_as_float(hh & 0xffff0000u);
                uint32_t ll = bf2(r0, r1);
                int colB = (wn * 64 + ni * 8 + tcol) * 2;
                asm volatile("st.shared.u32 [%0], %1;" :: "r"(pb + AT_PH + colB), "r"(hh) : "memory");
                asm volatile("st.shared.u32 [%0], %1;" :: "r"(pb + AT_PL + colB), "r"(ll) : "memory");
            }
        }
    __syncthreads();

    // ---- PV: O = P * V  (M=128, N=64, K=128), V^T via ldmatrix.trans ----
    float oc[2][4][4];
#pragma unroll
    for (int mi = 0; mi < 2; ++mi)
#pragma unroll
        for (int ni = 0; ni < 4; ++ni)
#pragma unroll
            for (int q = 0; q < 4; ++q) oc[mi][ni][q] = 0.f;

    const int vrow_l = (lane & 7) + ((lane >> 3) & 1) * 8;   // + ks*16
    const int vcol_l = wn * 64 + ((lane >> 4) & 1) * 16;     // bytes; + p*32

#pragma unroll
    for (int ks = 0; ks < 8; ++ks) {
        uint32_t ph[2][4], pl[2][4];
#pragma unroll
        for (int mi = 0; mi < 2; ++mi) {
            uint32_t ad = sb + (uint32_t)((a_row + mi * 16) * AT_PPITCH + ks * 32) + a_off;
            ldsm4(ph[mi], ad + AT_PH);
            ldsm4(pl[mi], ad + AT_PL);
        }
#pragma unroll
        for (int p = 0; p < 2; ++p) {
            uint32_t vh4[4], vl4[4];
            uint32_t vd = sb + (uint32_t)((ks * 16 + vrow_l) * AT_PITCH) + vcol_l + p * 32;
            ldsm4t(vh4, vd + AT_VH);
            ldsm4t(vl4, vd + AT_VL);
#pragma unroll
            for (int mi = 0; mi < 2; ++mi) {
#pragma unroll
                for (int half = 0; half < 2; ++half) {
                    float* c4 = oc[mi][p * 2 + half];
                    mma_bf16(c4, ph[mi], &vh4[half * 2]);
                    mma_bf16(c4, ph[mi], &vl4[half * 2]);
                    mma_bf16(c4, pl[mi], &vh4[half * 2]);
                }
            }
        }
    }

    // ---- epilogue: normalize, split to bf16 hi/lo, store ----
#pragma unroll
    for (int mi = 0; mi < 2; ++mi)
#pragma unroll
        for (int hr = 0; hr < 2; ++hr) {
            int row = wm * 32 + mi * 16 + hr * 8 + trow;
            float iv = inv_[mi][hr];
            size_t ob = ((size_t)row * PN + n) * PD + h * PDK;
#pragma unroll
            for (int ni = 0; ni < 4; ++ni) {
                int col = wn * 32 + ni * 8 + tcol;
                float f0 = oc[mi][ni][hr * 2 + 0] * iv;
                float f1 = oc[mi][ni][hr * 2 + 1] * iv;
                uint32_t hh = bf2(f0, f1);
                float r0 = f0 - __uint_as_float(hh << 16);
                float r1 = f1 - __uint_as_float(hh & 0xffff0000u);
                *(uint32_t*)(Oh + ob + col) = hh;
                *(uint32_t*)(Ol + ob + col) = bf2(r0, r1);
            }
        }
}

// ---------------------------------------------------------------------------
extern "C" void kernel_launch(void* const* d_in, const int* in_sizes, int n_in,
                              void* d_out, int out_size)
{
    const float* query = (const float*)d_in[0];
    const float* key_i = (const float*)d_in[1];
    const float* value = (const float*)d_in[2];
    const float* Wq = (const float*)d_in[3];
    const float* bq = (const float*)d_in[4];
    const float* Wk = (const float*)d_in[5];
    const float* bk = (const float*)d_in[6];
    const float* Wv = (const float*)d_in[7];
    const float* bv = (const float*)d_in[8];
    const float* Wo = (const float*)d_in[9];
    const float* bo = (const float*)d_in[10];
    float* out = (float*)d_out;

    __nv_bfloat16 *xqh, *xql, *xkh, *xkl, *xvh, *xvl;
    __nv_bfloat16 *pqh, *pql, *pkh, *pkl, *pvh, *pvl, *ohp, *olp, *wh, *wl;
    cudaGetSymbolAddress((void**)&xqh, g_xq_h);
    cudaGetSymbolAddress((void**)&xql, g_xq_l);
    cudaGetSymbolAddress((void**)&xkh, g_xk_h);
    cudaGetSymbolAddress((void**)&xkl, g_xk_l);
    cudaGetSymbolAddress((void**)&xvh, g_xv_h);
    cudaGetSymbolAddress((void**)&xvl, g_xv_l);
    cudaGetSymbolAddress((void**)&pqh, g_pq_h);
    cudaGetSymbolAddress((void**)&pql, g_pq_l);
    cudaGetSymbolAddress((void**)&pkh, g_pk_h);
    cudaGetSymbolAddress((void**)&pkl, g_pk_l);
    cudaGetSymbolAddress((void**)&pvh, g_pv_h);
    cudaGetSymbolAddress((void**)&pvl, g_pv_l);
    cudaGetSymbolAddress((void**)&ohp, g_o_h);
    cudaGetSymbolAddress((void**)&olp, g_o_l);
    cudaGetSymbolAddress((void**)&wh,  g_wh);
    cudaGetSymbolAddress((void**)&wl,  g_wl);

    cudaFuncSetAttribute(gemm_bf16x3<true>,
                         cudaFuncAttributeMaxDynamicSharedMemorySize, GEMM_SMEM);
    cudaFuncSetAttribute(gemm_bf16x3<false>,
                         cudaFuncAttributeMaxDynamicSharedMemorySize, GEMM_SMEM);
    cudaFuncSetAttribute(attn_tc,
                         cudaFuncAttributeMaxDynamicSharedMemorySize, AT_SMEM);

    const int nbig = PM * PD / 4, nw = PD * PD / 4;
    dim3 gg(PD / 128, PM / 128);   // (8, 256)

    split_kernel<<<nbig / 1024, 256>>>(query, xqh, xql, nbig);
    split_kernel<<<nw / 1024, 256>>>(Wq, wh + 0 * (size_t)PD * PD, wl + 0 * (size_t)PD * PD, nw);
    split_kernel<<<nbig / 1024, 256>>>(key_i, xkh, xkl, nbig);
    split_kernel<<<nw / 1024, 256>>>(Wk, wh + 1 * (size_t)PD * PD, wl + 1 * (size_t)PD * PD, nw);
    split_kernel<<<nbig / 1024, 256>>>(value, xvh, xvl, nbig);

    gemm_bf16x3<true><<<gg, 128, GEMM_SMEM>>>(
        xqh, xql, wh + 0 * (size_t)PD * PD, wl + 0 * (size_t)PD * PD,
        bq, 0.125f, nullptr, pqh, pql);

    split_kernel<<<nw / 1024, 256>>>(Wv, wh + 2 * (size_t)PD * PD, wl + 2 * (size_t)PD * PD, nw);
    split_kernel<<<nw / 1024, 256>>>(Wo, wh + 3 * (size_t)PD * PD, wl + 3 * (size_t)PD * PD, nw);

    gemm_bf16x3<true><<<gg, 128, GEMM_SMEM>>>(
        xkh, xkl, wh + 1 * (size_t)PD * PD, wl + 1 * (size_t)PD * PD,
        bk, 1.0f, nullptr, pkh, pkl);
    gemm_bf16x3<true><<<gg, 128, GEMM_SMEM>>>(
        xvh, xvl, wh + 2 * (size_t)PD * PD, wl + 2 * (size_t)PD * PD,
        bv, 1.0f, nullptr, pvh, pvl);

    attn_tc<<<PH * PN, 256, AT_SMEM>>>(pqh, pql, pkh, pkl, pvh, pvl, ohp, olp);

    gemm_bf16x3<false><<<gg, 128, GEMM_SMEM>>>(
        ohp, olp, wh + 3 * (size_t)PD * PD, wl + 3 * (size_t)PD * PD,
        bo, 1.0f, out, nullptr, nullptr);
}